// round 15
// baseline (speedup 1.0000x reference)
#include <cuda_runtime.h>
#include <cstdint>
#include <math.h>

#define BB 64
#define SS 96
#define HH 1024
#define EE 512
#define VV 32000
#define TT 32
#define G3 3072
#define CTAN 128              // N tile per CTA
#define KC 32                 // K chunk (floats)
#define NBLK 250              // VV / CTAN
#define LDS 36                // smem row stride (floats) -> conflict-free fragments

// pre-split-A stage: AHI 2304 | ALO 2304 | W 4608 = 9216 floats, two stages
#define SP_ALO 2304
#define SP_W   4608
#define SP_FL  9216
#define DS_SP  (2 * SP_FL * 4)     // 73728 B -> 2 CTAs/SM
// raw-A stage (gi): A 2304 | W 4608 = 6912 floats, two stages
#define RW_W   2304
#define RW_FL  6912
#define DS_RW  (2 * RW_FL * 4)     // 55296 B

// ---------------- device scratch (small, step-written only; NO big weight statics) ----------------
__device__ float g_u[HH];
__device__ float g_cthi[BB * HH], g_ctlo[BB * HH];
__device__ float g_gictx[BB * G3];
__device__ float g_gi[BB * G3];
__device__ float g_gh[BB * G3];
__device__ float g_h[BB * HH];
__device__ float g_hhi[BB * HH], g_hlo[BB * HH];
__device__ float g_pv[BB * NBLK];
__device__ int   g_pi[BB * NBLK];

// ---------------- helpers ----------------
__device__ __forceinline__ float to_tf32(float v) {
    float r;
    asm("cvt.rna.tf32.f32 %0, %1;" : "=f"(r) : "f"(v));
    return r;
}
__device__ __forceinline__ void tsplit(float v, float* hi, float* lo) {
    float h = to_tf32(v);
    *hi = h;
    *lo = to_tf32(v - h);
}
__device__ __forceinline__ uint32_t smem_u32(const void* p) {
    uint32_t a;
    asm("{ .reg .u64 t; cvta.to.shared.u64 t, %1; cvt.u32.u64 %0, t; }" : "=r"(a) : "l"(p));
    return a;
}
#define CPA16(sa, ga) \
    asm volatile("cp.async.cg.shared.global [%0], [%1], 16;" :: "r"(sa), "l"(ga))

// mma.sync m16n8k8 tf32: D(16x8,f32) += A(16x8) * B(8x8)
__device__ __forceinline__ void mma_tf32(float* d, const float* a, float b0, float b1) {
    asm volatile(
        "mma.sync.aligned.m16n8k8.row.col.f32.tf32.tf32.f32 "
        "{%0,%1,%2,%3}, {%4,%5,%6,%7}, {%8,%9}, {%0,%1,%2,%3};"
        : "+f"(d[0]), "+f"(d[1]), "+f"(d[2]), "+f"(d[3])
        : "r"(__float_as_uint(a[0])), "r"(__float_as_uint(a[1])),
          "r"(__float_as_uint(a[2])), "r"(__float_as_uint(a[3])),
          "r"(__float_as_uint(b0)),   "r"(__float_as_uint(b1)));
}

// ---------------- init: h0 split + fake argmax partials (tok=1 at t=0) ----------------
__global__ void k_init(const float* __restrict__ eh) {
    int i = blockIdx.x * blockDim.x + threadIdx.x;
    if (i < BB * HH) {
        float v = eh[i];
        g_h[i] = v;
        tsplit(v, &g_hhi[i], &g_hlo[i]);
    }
    if (i < BB * NBLK) {
        bool first = (i % NBLK) == 0;
        g_pv[i] = first ? 1.f : 0.f;
        g_pi[i] = first ? 1 : 0x7fffffff;    // argmax -> index 1 = START token
    }
}

// ---------------- u = Ua^T Va ----------------
__global__ void __launch_bounds__(256) k_u(const float* __restrict__ Ua,
                                           const float* __restrict__ Va) {
    __shared__ float sva[HH];
    for (int i = threadIdx.x; i < HH; i += 256) sva[i] = Va[i];
    __syncthreads();
    int h = blockIdx.x * 256 + threadIdx.x;
    float acc = 0.f;
    for (int g = 0; g < HH; ++g) acc = fmaf(sva[g], Ua[(size_t)g * HH + h], acc);
    g_u[h] = acc;
}

// ---------------- attention (step-invariant), ctx pre-split ----------------
__global__ void __launch_bounds__(128) k_attn(const float* __restrict__ keys,
                                              float* __restrict__ out_attn) {
    __shared__ float s_w[SS];
    __shared__ float s_u[HH];
    int b = blockIdx.x, tid = threadIdx.x;
    for (int i = tid; i < HH; i += 128) s_u[i] = g_u[i];
    __syncthreads();
    int warp = tid >> 5, lane = tid & 31;
    const float* kb = keys + (size_t)b * SS * HH;
    for (int s = warp; s < SS; s += 4) {
        const float* kr = kb + (size_t)s * HH;
        float acc = 0.f;
        for (int k = lane; k < HH; k += 32) acc = fmaf(kr[k], s_u[k], acc);
        #pragma unroll
        for (int o = 16; o; o >>= 1) acc += __shfl_down_sync(0xffffffffu, acc, o);
        if (!lane) s_w[s] = acc;
    }
    __syncthreads();
    if (warp == 0) {
        float m = -1e30f;
        for (int s = lane; s < SS; s += 32) m = fmaxf(m, s_w[s]);
        #pragma unroll
        for (int o = 16; o; o >>= 1) m = fmaxf(m, __shfl_xor_sync(0xffffffffu, m, o));
        float sum = 0.f;
        for (int s = lane; s < SS; s += 32) { float e = expf(s_w[s] - m); s_w[s] = e; sum += e; }
        #pragma unroll
        for (int o = 16; o; o >>= 1) sum += __shfl_xor_sync(0xffffffffu, sum, o);
        float inv = 1.f / sum;
        for (int s = lane; s < SS; s += 32) s_w[s] *= inv;
    }
    __syncthreads();
    for (int h = tid; h < HH; h += 128) {
        float acc = 0.f;
        for (int s = 0; s < SS; ++s) acc = fmaf(s_w[s], kb[(size_t)s * HH + h], acc);
        tsplit(acc, &g_cthi[b * HH + h], &g_ctlo[b * HH + h]);
    }
    float* oa = out_attn + (size_t)b * TT * SS;
    for (int e = tid; e < TT * SS; e += 128) oa[e] = s_w[e % SS];
}

// ============ split-TF32 GEMM, pre-split A path (logits / gh / gictx) ============
// out[64,128] = A @ W[n0..n0+127,:]^T.  acc += aH*bH + aH*bL + aL*bH (R13-validated).
__device__ __forceinline__ void mm_sp(
    const float* __restrict__ Ahi, const float* __restrict__ Alo, int lda,
    const float* __restrict__ W, int ldw,
    int NC, int n0,
    float* __restrict__ outAcc,
    const float* __restrict__ bias, float* __restrict__ outL, int t, int bx)
{
    extern __shared__ float sm[];
    const int tid = threadIdx.x;
    const int wid = tid >> 5, lane = tid & 31;
    const int wm = wid >> 2, wn = wid & 3;
    const int gid = lane >> 2, tig = lane & 3;
    const uint32_t smu = smem_u32(sm);

    float d[2][4][4];
    #pragma unroll
    for (int mt = 0; mt < 2; ++mt)
        #pragma unroll
        for (int nt = 0; nt < 4; ++nt)
            #pragma unroll
            for (int e = 0; e < 4; ++e) d[mt][nt][e] = 0.f;

    auto load_stage = [&](int j) {
        const uint32_t base = smu + ((j & 1) * SP_FL) * 4;
        int k0 = j * KC;
        #pragma unroll
        for (int q = 0; q < 2; ++q) {               // A hi+lo: 512+512 tasks
            int i = q * 256 + tid;
            int r = i >> 3, s = (i & 7) * 4;
            size_t go = (size_t)r * lda + k0 + s;
            CPA16(base + (r * LDS + s) * 4, Ahi + go);
            CPA16(base + (SP_ALO + r * LDS + s) * 4, Alo + go);
        }
        #pragma unroll
        for (int q = 0; q < 4; ++q) {               // W: 1024 tasks
            int i = q * 256 + tid;
            int r = i >> 3, s = (i & 7) * 4;
            CPA16(base + (SP_W + r * LDS + s) * 4, W + (size_t)(n0 + r) * ldw + k0 + s);
        }
        asm volatile("cp.async.commit_group;" ::: "memory");
    };

    load_stage(0);
    if (NC > 1) load_stage(1);

    for (int j = 0; j < NC; ++j) {
        if (j + 1 < NC) asm volatile("cp.async.wait_group 1;" ::: "memory");
        else            asm volatile("cp.async.wait_group 0;" ::: "memory");
        __syncthreads();

        const float* sAh = sm + (j & 1) * SP_FL;
        const float* sAl = sAh + SP_ALO;
        const float* sW  = sAh + SP_W;

        #pragma unroll
        for (int kt = 0; kt < KC / 8; ++kt) {
            const int c0 = kt * 8 + tig;
            float aH[2][4], aL[2][4];
            #pragma unroll
            for (int mt = 0; mt < 2; ++mt) {
                int ro = (wm * 32 + mt * 16 + gid) * LDS;
                aH[mt][0] = sAh[ro + c0];           aL[mt][0] = sAl[ro + c0];
                aH[mt][1] = sAh[ro + 8 * LDS + c0]; aL[mt][1] = sAl[ro + 8 * LDS + c0];
                aH[mt][2] = sAh[ro + c0 + 4];       aL[mt][2] = sAl[ro + c0 + 4];
                aH[mt][3] = sAh[ro + 8 * LDS + c0 + 4]; aL[mt][3] = sAl[ro + 8 * LDS + c0 + 4];
            }
            #pragma unroll
            for (int nt = 0; nt < 4; ++nt) {
                const float* wr = sW + (wn * 32 + nt * 8 + gid) * LDS;
                float w0 = wr[c0], w1 = wr[c0 + 4];
                float bH0 = to_tf32(w0), bL0 = to_tf32(w0 - bH0);
                float bH1 = to_tf32(w1), bL1 = to_tf32(w1 - bH1);
                #pragma unroll
                for (int mt = 0; mt < 2; ++mt) {
                    mma_tf32(d[mt][nt], aH[mt], bH0, bH1);
                    mma_tf32(d[mt][nt], aH[mt], bL0, bL1);
                    mma_tf32(d[mt][nt], aL[mt], bH0, bH1);
                }
            }
        }
        __syncthreads();
        if (j + 2 < NC) load_stage(j + 2);
    }

    // ---- epilogue ----
    float* sbuf = sm;
    #pragma unroll
    for (int mt = 0; mt < 2; ++mt)
        #pragma unroll
        for (int nt = 0; nt < 4; ++nt) {
            int row = wm * 32 + mt * 16 + gid;
            int col = wn * 32 + nt * 8 + 2 * tig;
            *(float2*)&sbuf[row * CTAN + col]       = make_float2(d[mt][nt][0], d[mt][nt][1]);
            *(float2*)&sbuf[(row + 8) * CTAN + col] = make_float2(d[mt][nt][2], d[mt][nt][3]);
        }
    __syncthreads();

    if (outAcc) {
        for (int i = tid; i < 64 * CTAN; i += 256) {
            int b = i >> 7, n = i & 127;
            outAcc[(size_t)b * G3 + n0 + n] = sbuf[i];
        }
        return;
    }

    int b = tid >> 2, cs = (tid & 3) * 32;
    float* out = outL + (size_t)b * TT * VV + (size_t)t * VV + n0;
    float bestv = -1e30f; int besti = 0;
    #pragma unroll
    for (int n = cs; n < cs + 32; n += 4) {
        float4 v = *(float4*)&sbuf[b * CTAN + n];
        float4 bi = *(const float4*)&bias[n0 + n];
        v.x += bi.x; v.y += bi.y; v.z += bi.z; v.w += bi.w;
        *(float4*)(out + n) = v;
        if (v.x > bestv) { bestv = v.x; besti = n0 + n; }
        if (v.y > bestv) { bestv = v.y; besti = n0 + n + 1; }
        if (v.z > bestv) { bestv = v.z; besti = n0 + n + 2; }
        if (v.w > bestv) { bestv = v.w; besti = n0 + n + 3; }
    }
    #pragma unroll
    for (int o = 1; o <= 2; o <<= 1) {
        float ov = __shfl_xor_sync(0xffffffffu, bestv, o);
        int   oi = __shfl_xor_sync(0xffffffffu, besti, o);
        if (ov > bestv || (ov == bestv && oi < besti)) { bestv = ov; besti = oi; }
    }
    if ((tid & 3) == 0) {
        g_pv[b * NBLK + bx] = bestv;
        g_pi[b * NBLK + bx] = besti;
    }
}

// fused per step: logits (bx<250) + gh (bx in [250,274)) -> 274 CTAs, single wave
__global__ void __launch_bounds__(256, 2) k_mm_logits(const float* __restrict__ W_out,
                                                      const float* __restrict__ b_out,
                                                      const float* __restrict__ W_hh,
                                                      float* __restrict__ outL, int t) {
    int bx = blockIdx.x;
    if (bx < NBLK)
        mm_sp(g_hhi, g_hlo, HH, W_out, HH, HH / KC, bx * CTAN,
              nullptr, b_out, outL, t, bx);
    else
        mm_sp(g_hhi, g_hlo, HH, W_hh, HH, HH / KC, (bx - NBLK) * CTAN,
              g_gh, nullptr, nullptr, 0, 0);
}
__global__ void __launch_bounds__(256, 2) k_mm_gh(const float* __restrict__ W_hh) {
    mm_sp(g_hhi, g_hlo, HH, W_hh, HH, HH / KC, blockIdx.x * CTAN,
          g_gh, nullptr, nullptr, 0, 0);
}
__global__ void __launch_bounds__(256, 2) k_mm_gictx(const float* __restrict__ W_ih) {
    mm_sp(g_cthi, g_ctlo, HH, W_ih + EE, EE + HH, HH / KC, blockIdx.x * CTAN,
          g_gictx, nullptr, nullptr, 0, 0);
}

// ============ gi kernel: inline argmax -> emb gather (raw A, relu+split in-loop) ============
__global__ void __launch_bounds__(256, 2) k_mm_gi(const float* __restrict__ embt,
                                                  const float* __restrict__ W_ih) {
    extern __shared__ float sm[];
    __shared__ int stok[BB];
    const int tid = threadIdx.x;
    const int wid = tid >> 5, lane = tid & 31;
    const int wm = wid >> 2, wn = wid & 3;
    const int gid = lane >> 2, tig = lane & 3;
    const uint32_t smu = smem_u32(sm);
    const int n0 = blockIdx.x * CTAN;

    // ---- inline argmax over partials: 4 threads per batch row ----
    {
        int b = tid >> 2, part = tid & 3;
        float v = -1e30f; int ix = 0x7fffffff;
        for (int p = part; p < NBLK; p += 4) {
            float pv = g_pv[b * NBLK + p]; int pi = g_pi[b * NBLK + p];
            if (pv > v || (pv == v && pi < ix)) { v = pv; ix = pi; }
        }
        #pragma unroll
        for (int o = 1; o <= 2; o <<= 1) {
            float ov = __shfl_xor_sync(0xffffffffu, v, o);
            int   oi = __shfl_xor_sync(0xffffffffu, ix, o);
            if (ov > v || (ov == v && oi < ix)) { v = ov; ix = oi; }
        }
        if (part == 0) stok[b] = ix;
    }
    __syncthreads();

    float d[2][4][4];
    #pragma unroll
    for (int mt = 0; mt < 2; ++mt)
        #pragma unroll
        for (int nt = 0; nt < 4; ++nt)
            #pragma unroll
            for (int e = 0; e < 4; ++e) d[mt][nt][e] = 0.f;

    const int NC = EE / KC;   // 16
    auto load_stage = [&](int j) {
        const uint32_t base = smu + ((j & 1) * RW_FL) * 4;
        int k0 = j * KC;
        #pragma unroll
        for (int q = 0; q < 2; ++q) {               // A (gathered emb rows): 512 tasks
            int i = q * 256 + tid;
            int r = i >> 3, s = (i & 7) * 4;
            CPA16(base + (r * LDS + s) * 4, embt + (size_t)stok[r] * EE + k0 + s);
        }
        #pragma unroll
        for (int q = 0; q < 4; ++q) {               // W: 1024 tasks
            int i = q * 256 + tid;
            int r = i >> 3, s = (i & 7) * 4;
            CPA16(base + (RW_W + r * LDS + s) * 4, W_ih + (size_t)(n0 + r) * (EE + HH) + k0 + s);
        }
        asm volatile("cp.async.commit_group;" ::: "memory");
    };

    load_stage(0);
    load_stage(1);

    for (int j = 0; j < NC; ++j) {
        if (j + 1 < NC) asm volatile("cp.async.wait_group 1;" ::: "memory");
        else            asm volatile("cp.async.wait_group 0;" ::: "memory");
        __syncthreads();

        const float* rawA = sm + (j & 1) * RW_FL;
        const float* rawW = rawA + RW_W;

        #pragma unroll
        for (int kt = 0; kt < KC / 8; ++kt) {
            const int c0 = kt * 8 + tig;
            float aH[2][4], aL[2][4];
            #pragma unroll
            for (int mt = 0; mt < 2; ++mt) {
                const float* ar = rawA + (wm * 32 + mt * 16 + gid) * LDS;
                float v0 = fmaxf(ar[c0], 0.f),           v1 = fmaxf(ar[8 * LDS + c0], 0.f);
                float v2 = fmaxf(ar[c0 + 4], 0.f),       v3 = fmaxf(ar[8 * LDS + c0 + 4], 0.f);
                aH[mt][0] = to_tf32(v0); aL[mt][0] = to_tf32(v0 - aH[mt][0]);
                aH[mt][1] = to_tf32(v1); aL[mt][1] = to_tf32(v1 - aH[mt][1]);
                aH[mt][2] = to_tf32(v2); aL[mt][2] = to_tf32(v2 - aH[mt][2]);
                aH[mt][3] = to_tf32(v3); aL[mt][3] = to_tf32(v3 - aH[mt][3]);
            }
            #pragma unroll
            for (int nt = 0; nt < 4; ++nt) {
                const float* wr = rawW + (wn * 32 + nt * 8 + gid) * LDS;
                float w0 = wr[c0], w1 = wr[c0 + 4];
                float bH0 = to_tf32(w0), bL0 = to_tf32(w0 - bH0);
                float bH1 = to_tf32(w1), bL1 = to_tf32(w1 - bH1);
                #pragma unroll
                for (int mt = 0; mt < 2; ++mt) {
                    mma_tf32(d[mt][nt], aH[mt], bH0, bH1);
                    mma_tf32(d[mt][nt], aH[mt], bL0, bL1);
                    mma_tf32(d[mt][nt], aL[mt], bH0, bH1);
                }
            }
        }
        __syncthreads();
        if (j + 2 < NC) load_stage(j + 2);
    }

    float* sbuf = sm;
    #pragma unroll
    for (int mt = 0; mt < 2; ++mt)
        #pragma unroll
        for (int nt = 0; nt < 4; ++nt) {
            int row = wm * 32 + mt * 16 + gid;
            int col = wn * 32 + nt * 8 + 2 * tig;
            *(float2*)&sbuf[row * CTAN + col]       = make_float2(d[mt][nt][0], d[mt][nt][1]);
            *(float2*)&sbuf[(row + 8) * CTAN + col] = make_float2(d[mt][nt][2], d[mt][nt][3]);
        }
    __syncthreads();
    for (int i = tid; i < 64 * CTAN; i += 256) {
        int b = i >> 7, n = i & 127;
        g_gi[(size_t)b * G3 + n0 + n] = sbuf[i];
    }
}

// ---------------- GRU gates: compose, update h, write splits ----------------
__global__ void __launch_bounds__(256) k_gates(const float* __restrict__ b_ih,
                                               const float* __restrict__ b_hh,
                                               float* __restrict__ out_h) {
    int idx = blockIdx.x * 256 + threadIdx.x;   // < 65536
    int b = idx >> 10, i = idx & 1023;
    int base = b * G3;
    float gir = g_gi[base + i]        + g_gictx[base + i]        + b_ih[i];
    float giz = g_gi[base + 1024 + i] + g_gictx[base + 1024 + i] + b_ih[1024 + i];
    float gin = g_gi[base + 2048 + i] + g_gictx[base + 2048 + i] + b_ih[2048 + i];
    float ghr = g_gh[base + i]        + b_hh[i];
    float ghz = g_gh[base + 1024 + i] + b_hh[1024 + i];
    float ghn = g_gh[base + 2048 + i] + b_hh[2048 + i];
    float r = 1.f / (1.f + expf(-(gir + ghr)));
    float z = 1.f / (1.f + expf(-(giz + ghz)));
    float n = tanhf(gin + r * ghn);
    float hn = (1.f - z) * n + z * g_h[idx];
    g_h[idx] = hn;
    tsplit(hn, &g_hhi[idx], &g_hlo[idx]);
    if (out_h) out_h[idx] = hn;
}

// ---------------- host ----------------
extern "C" void kernel_launch(void* const* d_in, const int* in_sizes, int n_in,
                              void* d_out, int out_size) {
    const float* enc   = (const float*)d_in[0];
    const float* eh    = (const float*)d_in[1];
    const float* embt  = (const float*)d_in[2];
    // d_in[3] = Wa: dead code (softmax shift invariance)
    const float* Ua    = (const float*)d_in[4];
    const float* Va    = (const float*)d_in[5];
    const float* W_ih  = (const float*)d_in[6];
    const float* W_hh  = (const float*)d_in[7];
    const float* b_ih  = (const float*)d_in[8];
    const float* b_hh  = (const float*)d_in[9];
    const float* W_out = (const float*)d_in[10];
    const float* b_out = (const float*)d_in[11];

    float* outL = (float*)d_out;
    float* outH = outL + (size_t)BB * TT * VV;
    float* outA = outH + (size_t)BB * HH;

    cudaFuncSetAttribute(k_mm_logits, cudaFuncAttributeMaxDynamicSharedMemorySize, DS_SP);
    cudaFuncSetAttribute(k_mm_gh,     cudaFuncAttributeMaxDynamicSharedMemorySize, DS_SP);
    cudaFuncSetAttribute(k_mm_gictx,  cudaFuncAttributeMaxDynamicSharedMemorySize, DS_SP);
    cudaFuncSetAttribute(k_mm_gi,     cudaFuncAttributeMaxDynamicSharedMemorySize, DS_RW);

    k_init<<<(BB * HH + 255) / 256, 256>>>(eh);
    k_u<<<HH / 256, 256>>>(Ua, Va);
    k_attn<<<BB, 128>>>(enc, outA);
    k_mm_gictx<<<G3 / CTAN, 256, DS_SP>>>(W_ih);
    k_mm_gh<<<G3 / CTAN, 256, DS_SP>>>(W_hh);      // gh(h0)
    k_mm_gi<<<G3 / CTAN, 256, DS_RW>>>(embt, W_ih); // gi(tok0=START via seeded partials)

    for (int t = 0; t < TT; ++t) {
        k_gates<<<BB * HH / 256, 256>>>(b_ih, b_hh, (t == TT - 1) ? outH : nullptr);
        k_mm_logits<<<NBLK + G3 / CTAN, 256, DS_SP>>>(W_out, b_out, W_hh, outL, t);
        if (t < TT - 1) k_mm_gi<<<G3 / CTAN, 256, DS_RW>>>(embt, W_ih);
    }
}

// round 16
// speedup vs baseline: 1.1705x; 1.1705x over previous
#include <cuda_runtime.h>
#include <cstdint>
#include <math.h>

#define BB 64
#define SS 96
#define HH 1024
#define EE 512
#define VV 32000
#define TT 32
#define G3 3072
#define CTAN 128              // N tile per CTA
#define KC 32                 // K chunk (floats)
#define NBLK 250              // VV / CTAN
#define LDS 36                // smem row stride (floats) -> conflict-free fragments
// raw stage: A[64x36]=2304 + W[128x36]=4608 = 6912 floats; two stages
#define RAW_W   2304
#define RAW_FL  6912
#define DSMEM_BYTES (2 * RAW_FL * 4)      // 55296 B -> 2 CTAs/SM

// ---------------- device scratch (small, step-written only; NO big statics) ----------------
__device__ float g_u[HH];
__device__ float g_ctx[BB * HH];
__device__ float g_gictx[BB * G3];
__device__ float g_giA[BB * G3];
__device__ float g_giB[BB * G3];
__device__ float g_ghA[BB * G3];
__device__ float g_ghB[BB * G3];
__device__ float g_h[BB * HH];
__device__ float g_pv[BB * NBLK];
__device__ int   g_pi[BB * NBLK];

// ---------------- helpers ----------------
__device__ __forceinline__ float to_tf32(float v) {
    float r;
    asm("cvt.rna.tf32.f32 %0, %1;" : "=f"(r) : "f"(v));
    return r;
}
__device__ __forceinline__ uint32_t smem_u32(const void* p) {
    uint32_t a;
    asm("{ .reg .u64 t; cvta.to.shared.u64 t, %1; cvt.u32.u64 %0, t; }" : "=r"(a) : "l"(p));
    return a;
}
#define CPA16(sa, ga) \
    asm volatile("cp.async.cg.shared.global [%0], [%1], 16;" :: "r"(sa), "l"(ga))

// mma.sync m16n8k8 tf32: D(16x8,f32) += A(16x8) * B(8x8)
__device__ __forceinline__ void mma_tf32(float* d, const float* a, float b0, float b1) {
    asm volatile(
        "mma.sync.aligned.m16n8k8.row.col.f32.tf32.tf32.f32 "
        "{%0,%1,%2,%3}, {%4,%5,%6,%7}, {%8,%9}, {%0,%1,%2,%3};"
        : "+f"(d[0]), "+f"(d[1]), "+f"(d[2]), "+f"(d[3])
        : "r"(__float_as_uint(a[0])), "r"(__float_as_uint(a[1])),
          "r"(__float_as_uint(a[2])), "r"(__float_as_uint(a[3])),
          "r"(__float_as_uint(b0)),   "r"(__float_as_uint(b1)));
}

// ---------------- init: h0 + seeded argmax partials (tok=1 at t=0) ----------------
__global__ void k_init(const float* __restrict__ eh) {
    int i = blockIdx.x * blockDim.x + threadIdx.x;
    if (i < BB * HH) g_h[i] = eh[i];
    if (i < BB * NBLK) {
        bool first = (i % NBLK) == 0;
        g_pv[i] = first ? 1.f : 0.f;
        g_pi[i] = first ? 1 : 0x7fffffff;    // argmax -> index 1 = START token
    }
}

// ---------------- u = Ua^T Va ----------------
__global__ void __launch_bounds__(256) k_u(const float* __restrict__ Ua,
                                           const float* __restrict__ Va) {
    __shared__ float sva[HH];
    for (int i = threadIdx.x; i < HH; i += 256) sva[i] = Va[i];
    __syncthreads();
    int h = blockIdx.x * 256 + threadIdx.x;
    float acc = 0.f;
    for (int g = 0; g < HH; ++g) acc = fmaf(sva[g], Ua[(size_t)g * HH + h], acc);
    g_u[h] = acc;
}

// ---------------- attention (step-invariant) ----------------
__global__ void __launch_bounds__(128) k_attn(const float* __restrict__ keys,
                                              float* __restrict__ out_attn) {
    __shared__ float s_w[SS];
    __shared__ float s_u[HH];
    int b = blockIdx.x, tid = threadIdx.x;
    for (int i = tid; i < HH; i += 128) s_u[i] = g_u[i];
    __syncthreads();
    int warp = tid >> 5, lane = tid & 31;
    const float* kb = keys + (size_t)b * SS * HH;
    for (int s = warp; s < SS; s += 4) {
        const float* kr = kb + (size_t)s * HH;
        float acc = 0.f;
        for (int k = lane; k < HH; k += 32) acc = fmaf(kr[k], s_u[k], acc);
        #pragma unroll
        for (int o = 16; o; o >>= 1) acc += __shfl_down_sync(0xffffffffu, acc, o);
        if (!lane) s_w[s] = acc;
    }
    __syncthreads();
    if (warp == 0) {
        float m = -1e30f;
        for (int s = lane; s < SS; s += 32) m = fmaxf(m, s_w[s]);
        #pragma unroll
        for (int o = 16; o; o >>= 1) m = fmaxf(m, __shfl_xor_sync(0xffffffffu, m, o));
        float sum = 0.f;
        for (int s = lane; s < SS; s += 32) { float e = expf(s_w[s] - m); s_w[s] = e; sum += e; }
        #pragma unroll
        for (int o = 16; o; o >>= 1) sum += __shfl_xor_sync(0xffffffffu, sum, o);
        float inv = 1.f / sum;
        for (int s = lane; s < SS; s += 32) s_w[s] *= inv;
    }
    __syncthreads();
    for (int h = tid; h < HH; h += 128) {
        float acc = 0.f;
        for (int s = 0; s < SS; ++s) acc = fmaf(s_w[s], kb[(size_t)s * HH + h], acc);
        g_ctx[b * HH + h] = acc;
    }
    float* oa = out_attn + (size_t)b * TT * SS;
    for (int e = tid; e < TT * SS; e += 128) oa[e] = s_w[e % SS];
}

// ============ split-TF32 GEMM, hand mma.m16n8k8 (raw A; lo terms HW-truncated) ============
__device__ __forceinline__ void mm_core(
    const float* __restrict__ A, int lda,
    const float* __restrict__ W, int ldw,
    int NC, int n0,
    float* __restrict__ outAcc,                                        // gates mode
    const float* __restrict__ bias, float* __restrict__ outL, int t, int bx)  // logits mode
{
    extern __shared__ float sm[];
    const int tid = threadIdx.x;
    const int wid = tid >> 5, lane = tid & 31;
    const int wm = wid >> 2, wn = wid & 3;
    const int gid = lane >> 2, tig = lane & 3;
    const uint32_t smu = smem_u32(sm);

    float d[2][4][4];
    #pragma unroll
    for (int mt = 0; mt < 2; ++mt)
        #pragma unroll
        for (int nt = 0; nt < 4; ++nt)
            #pragma unroll
            for (int e = 0; e < 4; ++e) d[mt][nt][e] = 0.f;

    auto load_stage = [&](int j) {
        const uint32_t base = smu + ((j & 1) * RAW_FL) * 4;
        int k0 = j * KC;
        #pragma unroll
        for (int q = 0; q < 2; ++q) {               // A: 512 f4 tasks (2/thread)
            int i = q * 256 + tid;
            int r = i >> 3, s = (i & 7) * 4;
            CPA16(base + (r * LDS + s) * 4, A + (size_t)r * lda + k0 + s);
        }
        #pragma unroll
        for (int q = 0; q < 4; ++q) {               // W: 1024 f4 tasks (4/thread)
            int i = q * 256 + tid;
            int r = i >> 3, s = (i & 7) * 4;
            CPA16(base + (RAW_W + r * LDS + s) * 4, W + (size_t)(n0 + r) * ldw + k0 + s);
        }
        asm volatile("cp.async.commit_group;" ::: "memory");
    };

    load_stage(0);
    if (NC > 1) load_stage(1);

    for (int j = 0; j < NC; ++j) {
        if (j + 1 < NC) asm volatile("cp.async.wait_group 1;" ::: "memory");
        else            asm volatile("cp.async.wait_group 0;" ::: "memory");
        __syncthreads();

        const float* rawA = sm + (j & 1) * RAW_FL;
        const float* rawW = rawA + RAW_W;

        #pragma unroll
        for (int kt = 0; kt < KC / 8; ++kt) {
            const int c0 = kt * 8 + tig;
            float aH[2][4], aL[2][4];
            #pragma unroll
            for (int mt = 0; mt < 2; ++mt) {
                const float* ar = rawA + (wm * 32 + mt * 16 + gid) * LDS;
                float v0 = ar[c0],           v1 = ar[8 * LDS + c0];
                float v2 = ar[c0 + 4],       v3 = ar[8 * LDS + c0 + 4];
                aH[mt][0] = to_tf32(v0); aL[mt][0] = v0 - aH[mt][0];
                aH[mt][1] = to_tf32(v1); aL[mt][1] = v1 - aH[mt][1];
                aH[mt][2] = to_tf32(v2); aL[mt][2] = v2 - aH[mt][2];
                aH[mt][3] = to_tf32(v3); aL[mt][3] = v3 - aH[mt][3];
            }
            #pragma unroll
            for (int nt = 0; nt < 4; ++nt) {
                const float* wr = rawW + (wn * 32 + nt * 8 + gid) * LDS;
                float w0 = wr[c0], w1 = wr[c0 + 4];
                float bH0 = to_tf32(w0), bL0 = w0 - bH0;
                float bH1 = to_tf32(w1), bL1 = w1 - bH1;
                #pragma unroll
                for (int mt = 0; mt < 2; ++mt) {
                    mma_tf32(d[mt][nt], aH[mt], bH0, bH1);
                    mma_tf32(d[mt][nt], aH[mt], bL0, bL1);
                    mma_tf32(d[mt][nt], aL[mt], bH0, bH1);
                }
            }
        }
        __syncthreads();
        if (j + 2 < NC) load_stage(j + 2);
    }

    // ---- epilogue: fragments -> smem [64][128] ----
    float* sbuf = sm;
    #pragma unroll
    for (int mt = 0; mt < 2; ++mt)
        #pragma unroll
        for (int nt = 0; nt < 4; ++nt) {
            int row = wm * 32 + mt * 16 + gid;
            int col = wn * 32 + nt * 8 + 2 * tig;
            *(float2*)&sbuf[row * CTAN + col]       = make_float2(d[mt][nt][0], d[mt][nt][1]);
            *(float2*)&sbuf[(row + 8) * CTAN + col] = make_float2(d[mt][nt][2], d[mt][nt][3]);
        }
    __syncthreads();

    if (outAcc) {   // gates mode
        for (int i = tid; i < 64 * CTAN; i += 256) {
            int b = i >> 7, n = i & 127;
            outAcc[(size_t)b * G3 + n0 + n] = sbuf[i];
        }
        return;
    }

    // logits mode: bias + store + per-row argmax partial
    int b = tid >> 2, cs = (tid & 3) * 32;
    float* out = outL + (size_t)b * TT * VV + (size_t)t * VV + n0;
    float bestv = -1e30f; int besti = 0;
    #pragma unroll
    for (int n = cs; n < cs + 32; n += 4) {
        float4 v = *(float4*)&sbuf[b * CTAN + n];
        float4 bi = *(const float4*)&bias[n0 + n];
        v.x += bi.x; v.y += bi.y; v.z += bi.z; v.w += bi.w;
        *(float4*)(out + n) = v;
        if (v.x > bestv) { bestv = v.x; besti = n0 + n; }
        if (v.y > bestv) { bestv = v.y; besti = n0 + n + 1; }
        if (v.z > bestv) { bestv = v.z; besti = n0 + n + 2; }
        if (v.w > bestv) { bestv = v.w; besti = n0 + n + 3; }
    }
    #pragma unroll
    for (int o = 1; o <= 2; o <<= 1) {
        float ov = __shfl_xor_sync(0xffffffffu, bestv, o);
        int   oi = __shfl_xor_sync(0xffffffffu, besti, o);
        if (ov > bestv || (ov == bestv && oi < besti)) { bestv = ov; besti = oi; }
    }
    if ((tid & 3) == 0) {
        g_pv[b * NBLK + bx] = bestv;
        g_pi[b * NBLK + bx] = besti;
    }
}

// gh dispatcher (used fused and standalone): bxr in [0,48)
__device__ __forceinline__ void gh_dispatch(int bxr, const float* __restrict__ W_hh) {
    if (bxr < 24)
        mm_core(g_h, HH, W_hh, HH, 512 / KC, bxr * CTAN,
                g_ghA, nullptr, nullptr, 0, 0);
    else
        mm_core(g_h + 512, HH, W_hh + 512, HH, 512 / KC, (bxr - 24) * CTAN,
                g_ghB, nullptr, nullptr, 0, 0);
}

// fused: logits (bx<250) + gh for next step (bx in [250,298))
__global__ void __launch_bounds__(256, 2) k_mm_logits(const float* __restrict__ W_out,
                                                      const float* __restrict__ b_out,
                                                      const float* __restrict__ W_hh,
                                                      float* __restrict__ outL, int t) {
    int bx = blockIdx.x;
    if (bx < NBLK)
        mm_core(g_h, HH, W_out, HH, HH / KC, bx * CTAN,
                nullptr, b_out, outL, t, bx);
    else
        gh_dispatch(bx - NBLK, W_hh);
}
__global__ void __launch_bounds__(256, 2) k_mm_gh(const float* __restrict__ W_hh) {
    gh_dispatch(blockIdx.x, W_hh);
}
__global__ void __launch_bounds__(256, 2) k_mm_gictx(const float* __restrict__ W_ih) {
    mm_core(g_ctx, HH, W_ih + EE, EE + HH, HH / KC, blockIdx.x * CTAN,
            g_gictx, nullptr, nullptr, 0, 0);
}

// ============ gi: inline argmax -> emb gather (relu in fragment load), K-split 48 CTAs ============
__global__ void __launch_bounds__(256, 2) k_mm_gi(const float* __restrict__ embt,
                                                  const float* __restrict__ W_ih) {
    extern __shared__ float sm[];
    __shared__ int stok[BB];
    const int tid = threadIdx.x;
    const int wid = tid >> 5, lane = tid & 31;
    const int wm = wid >> 2, wn = wid & 3;
    const int gid = lane >> 2, tig = lane & 3;
    const uint32_t smu = smem_u32(sm);
    const int bxr = blockIdx.x;
    const int half = (bxr >= 24);                 // 0: K[0,256) -> g_giA, 1: K[256,512) -> g_giB
    const int n0 = (half ? bxr - 24 : bxr) * CTAN;
    const int koff = half * 256;
    float* outAcc = half ? g_giB : g_giA;

    // ---- inline argmax over partials: 4 threads per batch row ----
    {
        int b = tid >> 2, part = tid & 3;
        float v = -1e30f; int ix = 0x7fffffff;
        for (int p = part; p < NBLK; p += 4) {
            float pv = g_pv[b * NBLK + p]; int pi = g_pi[b * NBLK + p];
            if (pv > v || (pv == v && pi < ix)) { v = pv; ix = pi; }
        }
        #pragma unroll
        for (int o = 1; o <= 2; o <<= 1) {
            float ov = __shfl_xor_sync(0xffffffffu, v, o);
            int   oi = __shfl_xor_sync(0xffffffffu, ix, o);
            if (ov > v || (ov == v && oi < ix)) { v = ov; ix = oi; }
        }
        if (part == 0) stok[b] = ix;
    }
    __syncthreads();

    float d[2][4][4];
    #pragma unroll
    for (int mt = 0; mt < 2; ++mt)
        #pragma unroll
        for (int nt = 0; nt < 4; ++nt)
            #pragma unroll
            for (int e = 0; e < 4; ++e) d[mt][nt][e] = 0.f;

    const int NC = 256 / KC;   // 8
    auto load_stage = [&](int j) {
        const uint32_t base = smu + ((j & 1) * RAW_FL) * 4;
        int k0 = koff + j * KC;
        #pragma unroll
        for (int q = 0; q < 2; ++q) {               // A (gathered emb rows)
            int i = q * 256 + tid;
            int r = i >> 3, s = (i & 7) * 4;
            CPA16(base + (r * LDS + s) * 4, embt + (size_t)stok[r] * EE + k0 + s);
        }
        #pragma unroll
        for (int q = 0; q < 4; ++q) {               // W
            int i = q * 256 + tid;
            int r = i >> 3, s = (i & 7) * 4;
            CPA16(base + (RAW_W + r * LDS + s) * 4,
                  W_ih + (size_t)(n0 + r) * (EE + HH) + k0 + s);
        }
        asm volatile("cp.async.commit_group;" ::: "memory");
    };

    load_stage(0);
    load_stage(1);

    for (int j = 0; j < NC; ++j) {
        if (j + 1 < NC) asm volatile("cp.async.wait_group 1;" ::: "memory");
        else            asm volatile("cp.async.wait_group 0;" ::: "memory");
        __syncthreads();

        const float* rawA = sm + (j & 1) * RAW_FL;
        const float* rawW = rawA + RAW_W;

        #pragma unroll
        for (int kt = 0; kt < KC / 8; ++kt) {
            const int c0 = kt * 8 + tig;
            float aH[2][4], aL[2][4];
            #pragma unroll
            for (int mt = 0; mt < 2; ++mt) {
                const float* ar = rawA + (wm * 32 + mt * 16 + gid) * LDS;
                float v0 = fmaxf(ar[c0], 0.f),     v1 = fmaxf(ar[8 * LDS + c0], 0.f);
                float v2 = fmaxf(ar[c0 + 4], 0.f), v3 = fmaxf(ar[8 * LDS + c0 + 4], 0.f);
                aH[mt][0] = to_tf32(v0); aL[mt][0] = v0 - aH[mt][0];
                aH[mt][1] = to_tf32(v1); aL[mt][1] = v1 - aH[mt][1];
                aH[mt][2] = to_tf32(v2); aL[mt][2] = v2 - aH[mt][2];
                aH[mt][3] = to_tf32(v3); aL[mt][3] = v3 - aH[mt][3];
            }
            #pragma unroll
            for (int nt = 0; nt < 4; ++nt) {
                const float* wr = rawW + (wn * 32 + nt * 8 + gid) * LDS;
                float w0 = wr[c0], w1 = wr[c0 + 4];
                float bH0 = to_tf32(w0), bL0 = w0 - bH0;
                float bH1 = to_tf32(w1), bL1 = w1 - bH1;
                #pragma unroll
                for (int mt = 0; mt < 2; ++mt) {
                    mma_tf32(d[mt][nt], aH[mt], bH0, bH1);
                    mma_tf32(d[mt][nt], aH[mt], bL0, bL1);
                    mma_tf32(d[mt][nt], aL[mt], bH0, bH1);
                }
            }
        }
        __syncthreads();
        if (j + 2 < NC) load_stage(j + 2);
    }

    float* sbuf = sm;
    #pragma unroll
    for (int mt = 0; mt < 2; ++mt)
        #pragma unroll
        for (int nt = 0; nt < 4; ++nt) {
            int row = wm * 32 + mt * 16 + gid;
            int col = wn * 32 + nt * 8 + 2 * tig;
            *(float2*)&sbuf[row * CTAN + col]       = make_float2(d[mt][nt][0], d[mt][nt][1]);
            *(float2*)&sbuf[(row + 8) * CTAN + col] = make_float2(d[mt][nt][2], d[mt][nt][3]);
        }
    __syncthreads();
    for (int i = tid; i < 64 * CTAN; i += 256) {
        int b = i >> 7, n = i & 127;
        outAcc[(size_t)b * G3 + n0 + n] = sbuf[i];
    }
}

// ---------------- GRU gates ----------------
__global__ void __launch_bounds__(256) k_gates(const float* __restrict__ b_ih,
                                               const float* __restrict__ b_hh,
                                               float* __restrict__ out_h) {
    int idx = blockIdx.x * 256 + threadIdx.x;   // < 65536
    int b = idx >> 10, i = idx & 1023;
    int base = b * G3;
    float gir = g_giA[base + i]        + g_giB[base + i]        + g_gictx[base + i]        + b_ih[i];
    float giz = g_giA[base + 1024 + i] + g_giB[base + 1024 + i] + g_gictx[base + 1024 + i] + b_ih[1024 + i];
    float gin = g_giA[base + 2048 + i] + g_giB[base + 2048 + i] + g_gictx[base + 2048 + i] + b_ih[2048 + i];
    float ghr = g_ghA[base + i]        + g_ghB[base + i]        + b_hh[i];
    float ghz = g_ghA[base + 1024 + i] + g_ghB[base + 1024 + i] + b_hh[1024 + i];
    float ghn = g_ghA[base + 2048 + i] + g_ghB[base + 2048 + i] + b_hh[2048 + i];
    float r = 1.f / (1.f + expf(-(gir + ghr)));
    float z = 1.f / (1.f + expf(-(giz + ghz)));
    float n = tanhf(gin + r * ghn);
    float hn = (1.f - z) * n + z * g_h[idx];
    g_h[idx] = hn;
    if (out_h) out_h[idx] = hn;
}

// ---------------- host ----------------
extern "C" void kernel_launch(void* const* d_in, const int* in_sizes, int n_in,
                              void* d_out, int out_size) {
    const float* enc   = (const float*)d_in[0];
    const float* eh    = (const float*)d_in[1];
    const float* embt  = (const float*)d_in[2];
    // d_in[3] = Wa: dead code (softmax shift invariance)
    const float* Ua    = (const float*)d_in[4];
    const float* Va    = (const float*)d_in[5];
    const float* W_ih  = (const float*)d_in[6];
    const float* W_hh  = (const float*)d_in[7];
    const float* b_ih  = (const float*)d_in[8];
    const float* b_hh  = (const float*)d_in[9];
    const float* W_out = (const float*)d_in[10];
    const float* b_out = (const float*)d_in[11];

    float* outL = (float*)d_out;
    float* outH = outL + (size_t)BB * TT * VV;
    float* outA = outH + (size_t)BB * HH;

    cudaFuncSetAttribute(k_mm_logits, cudaFuncAttributeMaxDynamicSharedMemorySize, DSMEM_BYTES);
    cudaFuncSetAttribute(k_mm_gh,     cudaFuncAttributeMaxDynamicSharedMemorySize, DSMEM_BYTES);
    cudaFuncSetAttribute(k_mm_gi,     cudaFuncAttributeMaxDynamicSharedMemorySize, DSMEM_BYTES);
    cudaFuncSetAttribute(k_mm_gictx,  cudaFuncAttributeMaxDynamicSharedMemorySize, DSMEM_BYTES);

    k_init<<<(BB * HH + 255) / 256, 256>>>(eh);
    k_u<<<HH / 256, 256>>>(Ua, Va);
    k_attn<<<BB, 128>>>(enc, outA);
    k_mm_gictx<<<G3 / CTAN, 256, DSMEM_BYTES>>>(W_ih);
    k_mm_gh<<<48, 256, DSMEM_BYTES>>>(W_hh);        // gh(h0)
    k_mm_gi<<<48, 256, DSMEM_BYTES>>>(embt, W_ih);  // gi(tok0=START via seeded partials)

    for (int t = 0; t < TT; ++t) {
        k_gates<<<BB * HH / 256, 256>>>(b_ih, b_hh, (t == TT - 1) ? outH : nullptr);
        k_mm_logits<<<NBLK + 48, 256, DSMEM_BYTES>>>(W_out, b_out, W_hh, outL, t);
        if (t < TT - 1) k_mm_gi<<<48, 256, DSMEM_BYTES>>>(embt, W_ih);
    }
}